// round 9
// baseline (speedup 1.0000x reference)
#include <cuda_runtime.h>
#include <cuda_fp16.h>
#include <cstdint>

#define DD 256      // feature/hidden dim
#define GD 768      // 3*DD gate dim
#define LL 96       // max group length
#define TG 14       // groups per block
#define BMAX 2048
#define NT 512      // threads per block (2 warpgroups: ih / hh)

typedef unsigned long long u64;

// ---------------- device scratch ----------------
__device__ int   g_order[BMAX * LL];          // edge id per (group, t), -1 = pad
__device__ uint2 g_wpack[4 * 64 * GD];        // fp16-packed: [mat][kb][gd] -> {w0|w1, w2|w3}

// ---------------- helpers ----------------
__device__ __forceinline__ u64 fma2(u64 a, u64 b, u64 c) {
    u64 d;
    asm("fma.rn.f32x2 %0, %1, %2, %3;" : "=l"(d) : "l"(a), "l"(b), "l"(c));
    return d;
}
__device__ __forceinline__ float red2(u64 a) {
    float lo = __uint_as_float((unsigned)(a & 0xffffffffULL));
    float hi = __uint_as_float((unsigned)(a >> 32));
    return lo + hi;
}
__device__ __forceinline__ u64 set_lo(float v) { return (u64)__float_as_uint(v); }

// expand 2 packed fp16 -> f32x2 register pair
__device__ __forceinline__ u64 hexp(uint32_t p) {
    __half2 h = *reinterpret_cast<const __half2*>(&p);
    float2  f = __half22float2(h);
    u64 r;
    asm("mov.b64 %0, {%1, %2};" : "=l"(r) : "f"(f.x), "f"(f.y));
    return r;
}

__device__ __forceinline__ float sigmoidf_(float v) {
    return __fdividef(1.f, 1.f + __expf(-v));
}
__device__ __forceinline__ float tanhf_(float v) {
    float t = __expf(2.f * v);
    return 1.f - __fdividef(2.f, t + 1.f);
}

__device__ __forceinline__ void cpa8(uint32_t dst, const void* src) {
    asm volatile("cp.async.ca.shared.global [%0], [%1], 8;\n" :: "r"(dst), "l"(src));
}
#define CPA_COMMIT() asm volatile("cp.async.commit_group;\n" ::)
#define CPA_WAIT1()  asm volatile("cp.async.wait_group 1;\n" ::: "memory")
#define CPA_WAIT0()  asm volatile("cp.async.wait_group 0;\n" ::: "memory")

// ---------------- fused setup: per-group timestamp sort + fp16 weight pack ----------------
__global__ void setup_k(const float* __restrict__ ts, const int* __restrict__ index,
                        int E, int B,
                        const float* __restrict__ w0, const float* __restrict__ w1,
                        const float* __restrict__ w2, const float* __restrict__ w3)
{
    const int b = blockIdx.x;
    if (b < B) {
        __shared__ int   lbub[2];
        __shared__ float sts[LL];
        const int i = threadIdx.x;
        if (i < 2) {
            const int key = b + i;
            int lo = 0, hi = E;
            while (lo < hi) {
                int m = (lo + hi) >> 1;
                if (index[m] < key) lo = m + 1; else hi = m;
            }
            lbub[i] = lo;
        }
        __syncthreads();
        const int off = lbub[0];
        const int c   = lbub[1] - lbub[0];
        if (i < c)  sts[i] = ts[off + i];
        if (i < LL) g_order[b * LL + i] = -1;
        __syncthreads();
        if (i < c) {
            const float ti = sts[i];
            int rank = 0;
            for (int j = 0; j < c; ++j) {
                float tj = sts[j];
                rank += (tj < ti || (tj == ti && j < i)) ? 1 : 0;
            }
            g_order[b * LL + (LL - c + rank)] = off + i;
        }
    } else {
        int idx = (b - B) * 256 + threadIdx.x;
        if (idx < 4 * 64 * GD) {
            int m   = idx / (64 * GD);
            int rem = idx - m * 64 * GD;
            int kb  = rem / GD;
            int dd  = rem - kb * GD;
            const float* W = (m == 0) ? w0 : (m == 1) ? w1 : (m == 2) ? w2 : w3;
            const float* p = W + dd * DD + kb * 4;
            __half2 h01 = __floats2half2_rn(p[0], p[1]);
            __half2 h23 = __floats2half2_rn(p[2], p[3]);
            uint2 q;
            q.x = *reinterpret_cast<uint32_t*>(&h01);
            q.y = *reinterpret_cast<uint32_t*>(&h23);
            g_wpack[idx] = q;
        }
    }
}

// ---------------- weight-stage prologue: issue kb0 into stage 0 ----------------
__device__ __forceinline__ void issue3(const uint2* __restrict__ wmat_d, uint32_t wsm_u32) {
    cpa8(wsm_u32,              wmat_d);
    cpa8(wsm_u32 + DD * 8,     wmat_d + DD);
    cpa8(wsm_u32 + 2 * DD * 8, wmat_d + 2 * DD);
    CPA_COMMIT();
}

// ---------------- 3-gate GEMM pass over 64 kb blocks ----------------
// A[3*TG] accumulators must be pre-initialized with biases.
template<bool PRO>
__device__ __forceinline__ void gemm3(
    const uint2* __restrict__ wmat_d,   // packed matrix base + d (element stride GD per kb)
    uint32_t wsm_u32,                   // smem byte addr of this thread's stage0/gate0 slot
    const uint2* __restrict__ wsm_p,    // same slot as a pointer
    const float* __restrict__ op0,      // operand base [TG][DD]
    u64* __restrict__ A)
{
    if (PRO) issue3(wmat_d, wsm_u32);

    const char* op = (const char*)op0;
#pragma unroll 1
    for (int kb = 0; kb < 64; ++kb) {
        if (kb < 63) {
            const uint2*   src = wmat_d + (size_t)(kb + 1) * GD;
            const uint32_t dst = wsm_u32 + ((kb + 1) & 1) * (6 * DD * 8);
            cpa8(dst,              src);
            cpa8(dst + DD * 8,     src + DD);
            cpa8(dst + 2 * DD * 8, src + 2 * DD);
            CPA_COMMIT();
            CPA_WAIT1();
        } else {
            CPA_WAIT0();
        }
        const uint2* wc = wsm_p + (kb & 1) * (6 * DD);
        const uint2 pr = wc[0];
        const uint2 pz = wc[DD];
        const uint2 pn = wc[2 * DD];
        const u64 wr0 = hexp(pr.x), wr1 = hexp(pr.y);
        const u64 wz0 = hexp(pz.x), wz1 = hexp(pz.y);
        const u64 wn0 = hexp(pn.x), wn1 = hexp(pn.y);
#pragma unroll
        for (int g = 0; g < TG; ++g) {
            ulonglong2 ov = *(const ulonglong2*)(op + g * (DD * 4));
            A[0 * TG + g] = fma2(wr0, ov.x, A[0 * TG + g]);
            A[0 * TG + g] = fma2(wr1, ov.y, A[0 * TG + g]);
            A[1 * TG + g] = fma2(wz0, ov.x, A[1 * TG + g]);
            A[1 * TG + g] = fma2(wz1, ov.y, A[1 * TG + g]);
            A[2 * TG + g] = fma2(wn0, ov.x, A[2 * TG + g]);
            A[2 * TG + g] = fma2(wn1, ov.y, A[2 * TG + g]);
        }
        op += 16;
    }
}

// ---------------- main persistent kernel ----------------
__global__ __launch_bounds__(NT, 1) void gru_main(
    const float* __restrict__ x,
    const float* __restrict__ bih0, const float* __restrict__ bhh0,
    const float* __restrict__ bih1, const float* __restrict__ bhh1,
    float* __restrict__ out, int B)
{
    extern __shared__ float sm[];
    float* xs   = sm;                       // [TG][DD]
    float* h0s  = sm + 1 * TG * DD;         // [TG][DD]
    float* h1s  = sm + 2 * TG * DD;         // [TG][DD]
    float* accs = sm + 3 * TG * DD;         // [TG][DD]
    float* phA  = sm + 4 * TG * DD;         // [TG][3][DD]
    float* phB  = sm + 7 * TG * DD;         // [TG][3][DD]
    uint2* wbuf = (uint2*)(sm + 10 * TG * DD);  // [2 stages][2 sides][3 gates][DD]

    const int tid  = threadIdx.x;
    const int side = tid >> 8;              // 0 = ih warpgroup, 1 = hh warpgroup
    const int d    = tid & (DD - 1);
    const int g0   = blockIdx.x * TG;

    // this thread's stage0/gate0 weight slot
    uint2*   wsm_p   = wbuf + side * (3 * DD) + d;
    uint32_t wsm_u32 = (uint32_t)__cvta_generic_to_shared(wsm_p);

    const float* bv0 = side ? bhh0 : bih0;
    const float* bv1 = side ? bhh1 : bih1;
    const float b0r = bv0[d], b0z = bv0[DD + d], b0n = bv0[2 * DD + d];
    const float b1r = bv1[d], b1z = bv1[DD + d], b1n = bv1[2 * DD + d];
    const uint2* w0d = g_wpack + (size_t)(side ? 1 : 0) * 64 * GD + d;  // L0 matrix, +d
    const uint2* w1d = g_wpack + (size_t)(side ? 3 : 2) * 64 * GD + d;  // L1 matrix, +d

    // zero h0s, h1s, accs (contiguous)
    for (int i = tid; i < 3 * TG * DD; i += NT) h0s[i] = 0.f;
    // gather xs(0) (all threads)
    for (int k = tid; k < TG * DD; k += NT) {
        const int g   = k >> 8;
        const int dd  = k & (DD - 1);
        const int grp = g0 + g;
        int e = (grp < B) ? g_order[grp * LL] : -1;
        xs[k] = (e >= 0) ? x[(size_t)e * DD + dd] : 0.f;
    }
    __syncthreads();

    u64 A[3 * TG];

#pragma unroll 1
    for (int t = 0; t < LL; ++t) {
        // ---- pass 0 (layer 0): ih streams xs, hh streams h0s ----
        {
            const u64 vr = set_lo(b0r), vz = set_lo(b0z), vn = set_lo(b0n);
#pragma unroll
            for (int g = 0; g < TG; ++g) { A[g] = vr; A[TG + g] = vz; A[2 * TG + g] = vn; }
        }
        gemm3<true>(w0d, wsm_u32, wsm_p, side ? h0s : xs, A);
        if (side) {
#pragma unroll
            for (int g = 0; g < TG; ++g) {
                float* p = phA + g * (3 * DD);
                p[d]          = red2(A[g]);
                p[DD + d]     = red2(A[TG + g]);
                p[2 * DD + d] = red2(A[2 * TG + g]);
            }
        }
        __syncthreads();   // sync1: phA visible; hh done reading h0s

        // pre-issue pass-1 weights (both sides) so the copy overlaps the epilogue
        issue3(w1d, wsm_u32);

        if (!side) {
            // L0 epilogue: combine, update h0s
#pragma unroll
            for (int g = 0; g < TG; ++g) {
                const float* p = phA + g * (3 * DD);
                float r  = sigmoidf_(red2(A[g]) + p[d]);
                float z  = sigmoidf_(red2(A[TG + g]) + p[DD + d]);
                float n  = tanhf_(fmaf(r, p[2 * DD + d], red2(A[2 * TG + g])));
                float h  = h0s[g * DD + d];
                h0s[g * DD + d] = fmaf(z, h - n, n);
            }
            asm volatile("bar.sync 1, 256;" ::: "memory");   // ih-internal: h0s complete
        }

        // ---- pass 1 (layer 1): ih streams new h0s, hh streams h1s ----
        {
            const u64 vr = set_lo(b1r), vz = set_lo(b1z), vn = set_lo(b1n);
#pragma unroll
            for (int g = 0; g < TG; ++g) { A[g] = vr; A[TG + g] = vz; A[2 * TG + g] = vn; }
        }
        gemm3<false>(w1d, wsm_u32, wsm_p, side ? h1s : h0s, A);
        if (side) {
#pragma unroll
            for (int g = 0; g < TG; ++g) {
                float* p = phB + g * (3 * DD);
                p[d]          = red2(A[g]);
                p[DD + d]     = red2(A[TG + g]);
                p[2 * DD + d] = red2(A[2 * TG + g]);
            }
        }
        __syncthreads();   // sync2: phB visible; hh done reading h1s

        if (!side) {
            // L1 epilogue: combine, update h1s + pooled acc
#pragma unroll
            for (int g = 0; g < TG; ++g) {
                const float* p = phB + g * (3 * DD);
                float r  = sigmoidf_(red2(A[g]) + p[d]);
                float z  = sigmoidf_(red2(A[TG + g]) + p[DD + d]);
                float n  = tanhf_(fmaf(r, p[2 * DD + d], red2(A[2 * TG + g])));
                float h  = h1s[g * DD + d];
                float hnew = fmaf(z, h - n, n);
                h1s[g * DD + d] = hnew;
                accs[g * DD + d] += hnew;
            }
        } else if (t + 1 < LL) {
            // hh gathers next step's x while ih runs the epilogue
            for (int k = tid - 256; k < TG * DD; k += 256) {
                const int g   = k >> 8;
                const int dd  = k & (DD - 1);
                const int grp = g0 + g;
                int e = (grp < B) ? g_order[grp * LL + t + 1] : -1;
                xs[k] = (e >= 0) ? x[(size_t)e * DD + dd] : 0.f;
            }
        }
        __syncthreads();   // sync3: h0s/h1s/xs consistent for next step
    }

    if (side == 0) {
#pragma unroll
        for (int g = 0; g < TG; ++g) {
            const int grp = g0 + g;
            if (grp < B) out[(size_t)grp * DD + d] = accs[g * DD + d] * (1.0f / LL);
        }
    }
}

// ---------------- entry point ----------------
extern "C" void kernel_launch(void* const* d_in, const int* in_sizes, int n_in,
                              void* d_out, int out_size) {
    const float* x     = (const float*)d_in[0];
    const float* ts    = (const float*)d_in[1];
    const float* wih0  = (const float*)d_in[2];
    const float* whh0  = (const float*)d_in[3];
    const float* bih0  = (const float*)d_in[4];
    const float* bhh0  = (const float*)d_in[5];
    const float* wih1  = (const float*)d_in[6];
    const float* whh1  = (const float*)d_in[7];
    const float* bih1  = (const float*)d_in[8];
    const float* bhh1  = (const float*)d_in[9];
    const int*   index = (const int*)d_in[10];
    float* out = (float*)d_out;

    const int E = in_sizes[0] / DD;
    const int B = out_size / DD;

    // smem: 10*TG*DD floats (state + 2x ph) + 2*2*3*DD uint2 weight stages
    const int smem = (10 * TG * DD) * (int)sizeof(float) + 12 * DD * (int)sizeof(uint2);
    cudaFuncSetAttribute(gru_main, cudaFuncAttributeMaxDynamicSharedMemorySize, smem);

    setup_k<<<B + 768, 256>>>(ts, index, E, B, wih0, whh0, wih1, whh1);

    int nb = (B + TG - 1) / TG;
    if (nb < 148) nb = 148;             // avoid sub-148-grid issue throttle
    gru_main<<<nb, NT, smem>>>(x, bih0, bhh0, bih1, bhh1, out, B);
}

// round 10
// speedup vs baseline: 2.6818x; 2.6818x over previous
#include <cuda_runtime.h>
#include <cuda_fp16.h>
#include <cstdint>

#define DD 256      // feature/hidden dim
#define GD 768      // 3*DD gate dim
#define LL 96       // max group length
#define TG 14       // groups per block
#define BMAX 2048
#define NT 512      // 16 warps
#define KC 32       // k8 chunks per K=256
#define MATB 12288  // bytes per matrix k8-chunk (768*8*2)
#define CHUNK_B 24576 // bytes per 2-matrix chunk
#define OPW 264     // halves per operand row (256 + 8 pad)

// ---- smem layout (bytes) ----
#define OFF_W    0                       // 3 stages x 24576
#define OFF_XH   73728                   // [16][264] half
#define OFF_H0H  (73728 + 8448)
#define OFF_H1H  (73728 + 16896)
#define OFF_SRZ  99072                   // [512][14] float (r,z combined sums)
#define OFF_XN   127744                  // [256][14] float
#define OFF_HN   142080                  // [256][14] float
#define SMEM_TOT 156416

typedef unsigned int u32;

// ---------------- device scratch ----------------
__device__ int    g_order[BMAX * LL];                  // edge id per (group,t), -1 = pad
__device__ __half g_wblob[2 * KC * (CHUNK_B / 2)];     // [layer][kc][mat][768][8] halves

// ---------------- helpers ----------------
__device__ __forceinline__ float sigmoidf_(float v) {
    return __fdividef(1.f, 1.f + __expf(-v));
}
__device__ __forceinline__ float tanhf_(float v) {
    float t = __expf(2.f * v);
    return 1.f - __fdividef(2.f, t + 1.f);
}
__device__ __forceinline__ void cpc16(u32 dst, const void* src) {
    asm volatile("cp.async.cg.shared.global [%0], [%1], 16;\n" :: "r"(dst), "l"(src));
}
#define CPA_COMMIT() asm volatile("cp.async.commit_group;\n" ::)
#define CPA_WAIT1()  asm volatile("cp.async.wait_group 1;\n" ::: "memory")

__device__ __forceinline__ void ldsm_x2(u32& r0, u32& r1, u32 addr) {
    asm volatile("ldmatrix.sync.aligned.m8n8.x2.shared.b16 {%0,%1}, [%2];"
                 : "=r"(r0), "=r"(r1) : "r"(addr));
}
__device__ __forceinline__ void mma8(float* c, u32 a0, u32 a1, u32 b0) {
    asm volatile("mma.sync.aligned.m16n8k8.row.col.f32.f16.f16.f32 "
                 "{%0,%1,%2,%3}, {%4,%5}, {%6}, {%0,%1,%2,%3};"
                 : "+f"(c[0]), "+f"(c[1]), "+f"(c[2]), "+f"(c[3])
                 : "r"(a0), "r"(a1), "r"(b0));
}

// ---------------- fused setup: per-group timestamp sort + fp16 weight blob ----------------
__global__ void setup_k(const float* __restrict__ ts, const int* __restrict__ index,
                        int E, int B,
                        const float* __restrict__ wih0, const float* __restrict__ whh0,
                        const float* __restrict__ wih1, const float* __restrict__ whh1)
{
    const int b = blockIdx.x;
    if (b < B) {
        __shared__ int   lbub[2];
        __shared__ float sts[LL];
        const int i = threadIdx.x;
        if (i < 2) {
            const int key = b + i;
            int lo = 0, hi = E;
            while (lo < hi) {
                int m = (lo + hi) >> 1;
                if (index[m] < key) lo = m + 1; else hi = m;
            }
            lbub[i] = lo;
        }
        __syncthreads();
        const int off = lbub[0];
        const int c   = lbub[1] - lbub[0];
        if (i < c)  sts[i] = ts[off + i];
        if (i < LL) g_order[b * LL + i] = -1;
        __syncthreads();
        if (i < c) {
            const float ti = sts[i];
            int rank = 0;
            for (int j = 0; j < c; ++j) {
                float tj = sts[j];
                rank += (tj < ti || (tj == ti && j < i)) ? 1 : 0;
            }
            g_order[b * LL + (LL - c + rank)] = off + i;
        }
    } else {
        int idx = (b - B) * 256 + threadIdx.x;     // 0 .. 786431
        if (idx < 2 * KC * 2 * GD * 8) {
            int p  = idx / 393216;  int r1 = idx % 393216;
            int c  = r1 / 12288;    int r2 = r1 % 12288;
            int m  = r2 / 6144;     int r3 = r2 % 6144;
            int row = r3 / 8;       int k8 = r3 % 8;
            const float* W = (p == 0) ? (m == 0 ? wih0 : whh0)
                                      : (m == 0 ? wih1 : whh1);
            g_wblob[idx] = __float2half_rn(W[row * DD + c * 8 + k8]);
        }
    }
}

// ---------------- one layer pass: G = W_ih@opA + W_hh@opB -> combine arrays ----------------
__device__ __forceinline__ void gemm_pass(
    const __half* __restrict__ wgl,     // blob base for this layer
    const __half* __restrict__ opA,     // [16][OPW] fp16 (input operand)
    const __half* __restrict__ opB,     // [16][OPW] fp16 (hidden operand)
    float* __restrict__ srz, float* __restrict__ sxn, float* __restrict__ shn,
    u32 wst_u32, int tid, int w, int lane)
{
    float cx[24], ch[24];
#pragma unroll
    for (int i = 0; i < 24; ++i) { cx[i] = 0.f; ch[i] = 0.f; }

    const char* wglc = (const char*)wgl;
    // prologue: chunks 0,1 -> stages 0,1
#pragma unroll
    for (int c = 0; c < 2; ++c) {
        const char* src = wglc + c * CHUNK_B + tid * 16;
        u32 dst = wst_u32 + c * CHUNK_B + tid * 16;
        cpc16(dst, src); cpc16(dst + 8192, src + 8192); cpc16(dst + 16384, src + 16384);
        CPA_COMMIT();
    }

    const int rsel = (lane & 15);
    const int bofA = (lane >> 2) * OPW + (lane & 3) * 2;   // half-index base (n8=0)

#pragma unroll 1
    for (int kc = 0; kc < KC; ++kc) {
        CPA_WAIT1();
        __syncthreads();
        if (kc + 2 < KC) {
            const char* src = wglc + (kc + 2) * CHUNK_B + tid * 16;
            u32 dst = wst_u32 + ((kc + 2) % 3) * CHUNK_B + tid * 16;
            cpc16(dst, src); cpc16(dst + 8192, src + 8192); cpc16(dst + 16384, src + 16384);
        }
        CPA_COMMIT();

        const u32 sbase = wst_u32 + (kc % 3) * CHUNK_B;
        // B fragments (direct b32 loads; op rows are [n][k] col-major for mma)
        const int kh = kc * 8;
        u32 bx0 = *(const u32*)(opA + bofA + kh);
        u32 bx1 = *(const u32*)(opA + bofA + 8 * OPW + kh);
        u32 bh0 = *(const u32*)(opB + bofA + kh);
        u32 bh1 = *(const u32*)(opB + bofA + 8 * OPW + kh);
#pragma unroll
        for (int j = 0; j < 3; ++j) {
            const int R = w * 48 + j * 16;
            u32 a0, a1;
            ldsm_x2(a0, a1, sbase + (u32)(R + rsel) * 16);          // W_ih tile
            mma8(&cx[(j * 2 + 0) * 4], a0, a1, bx0);
            mma8(&cx[(j * 2 + 1) * 4], a0, a1, bx1);
            ldsm_x2(a0, a1, sbase + MATB + (u32)(R + rsel) * 16);   // W_hh tile
            mma8(&ch[(j * 2 + 0) * 4], a0, a1, bh0);
            mma8(&ch[(j * 2 + 1) * 4], a0, a1, bh1);
        }
    }

    // publish: r,z bands -> combined sums; n band -> separate x/h partials
    const int r0  = lane >> 2;
    const int cp2 = (lane & 3) * 2;
#pragma unroll
    for (int j = 0; j < 3; ++j) {
        const int R = w * 48 + j * 16;
#pragma unroll
        for (int n = 0; n < 2; ++n) {
            const int col = n * 8 + cp2;
            if (col >= TG) continue;            // drop pad cols 14,15
            const float* cxp = &cx[(j * 2 + n) * 4];
            const float* chp = &ch[(j * 2 + n) * 4];
            if (R < 512) {
                *(float2*)&srz[(R + r0) * TG + col] =
                    make_float2(cxp[0] + chp[0], cxp[1] + chp[1]);
                *(float2*)&srz[(R + r0 + 8) * TG + col] =
                    make_float2(cxp[2] + chp[2], cxp[3] + chp[3]);
            } else {
                const int q = R - 512 + r0;
                *(float2*)&sxn[q * TG + col]       = make_float2(cxp[0], cxp[1]);
                *(float2*)&sxn[(q + 8) * TG + col] = make_float2(cxp[2], cxp[3]);
                *(float2*)&shn[q * TG + col]       = make_float2(chp[0], chp[1]);
                *(float2*)&shn[(q + 8) * TG + col] = make_float2(chp[2], chp[3]);
            }
        }
    }
    __syncthreads();
}

// ---------------- main persistent kernel ----------------
__global__ __launch_bounds__(NT, 1) void gru_main(
    const float* __restrict__ x,
    const float* __restrict__ bih0, const float* __restrict__ bhh0,
    const float* __restrict__ bih1, const float* __restrict__ bhh1,
    float* __restrict__ out, int B)
{
    extern __shared__ char sb[];
    __half* xh  = (__half*)(sb + OFF_XH);
    __half* h0h = (__half*)(sb + OFF_H0H);
    __half* h1h = (__half*)(sb + OFF_H1H);
    float*  srz = (float*)(sb + OFF_SRZ);
    float*  sxn = (float*)(sb + OFF_XN);
    float*  shn = (float*)(sb + OFF_HN);
    const u32 wst_u32 = (u32)__cvta_generic_to_shared(sb + OFF_W);

    const int tid  = threadIdx.x;
    const int w    = tid >> 5;
    const int lane = tid & 31;
    const int d    = tid & 255;
    const int gb   = tid >> 8;          // 0 or 1
    const int g0   = blockIdx.x * TG;

    // zero all operand halves (xh/h0h/h1h contiguous: 25344 B = 6336 words)
    for (int i = tid; i < 6336; i += NT) ((u32*)xh)[i] = 0;
    __syncthreads();

    // gather x(0)
#pragma unroll
    for (int i = 0; i < 7; ++i) {
        const int k  = tid + i * NT;
        const int g  = k >> 8, dd = k & 255;
        const int grp = g0 + g;
        const int e  = (grp < B) ? g_order[grp * LL] : -1;
        xh[g * OPW + dd] = (e >= 0) ? __float2half_rn(x[(size_t)e * DD + dd]) : __half(0.f);
    }

    // biases (per-d, in registers)
    const float br0 = bih0[d] + bhh0[d],           bz0 = bih0[DD + d] + bhh0[DD + d];
    const float bxn0 = bih0[2 * DD + d],           bhn0 = bhh0[2 * DD + d];
    const float br1 = bih1[d] + bhh1[d],           bz1 = bih1[DD + d] + bhh1[DD + d];
    const float bxn1 = bih1[2 * DD + d],           bhn1 = bhh1[2 * DD + d];

    float h0r[7], h1r[7], acc[7];
#pragma unroll
    for (int i = 0; i < 7; ++i) { h0r[i] = 0.f; h1r[i] = 0.f; acc[i] = 0.f; }
    __syncthreads();

    const __half* wb0 = g_wblob;
    const __half* wb1 = g_wblob + (size_t)KC * (CHUNK_B / 2);

#pragma unroll 1
    for (int t = 0; t < LL; ++t) {
        // ---- layer 0: G = W_ih0@x + W_hh0@h0 ----
        gemm_pass(wb0, xh, h0h, srz, sxn, shn, wst_u32, tid, w, lane);
#pragma unroll
        for (int i = 0; i < 7; ++i) {
            const int g = gb + 2 * i;
            float r = sigmoidf_(srz[d * TG + g] + br0);
            float z = sigmoidf_(srz[(DD + d) * TG + g] + bz0);
            float n = tanhf_(sxn[d * TG + g] + bxn0 + r * (shn[d * TG + g] + bhn0));
            float h = h0r[i];
            float hn2 = n + z * (h - n);
            h0r[i] = hn2;
            h0h[g * OPW + d] = __float2half_rn(hn2);
        }
        __syncthreads();

        // ---- layer 1: G = W_ih1@h0new + W_hh1@h1 ----
        gemm_pass(wb1, h0h, h1h, srz, sxn, shn, wst_u32, tid, w, lane);
#pragma unroll
        for (int i = 0; i < 7; ++i) {
            const int g = gb + 2 * i;
            float r = sigmoidf_(srz[d * TG + g] + br1);
            float z = sigmoidf_(srz[(DD + d) * TG + g] + bz1);
            float n = tanhf_(sxn[d * TG + g] + bxn1 + r * (shn[d * TG + g] + bhn1));
            float h = h1r[i];
            float hn2 = n + z * (h - n);
            h1r[i] = hn2;
            acc[i] += hn2;
            h1h[g * OPW + d] = __float2half_rn(hn2);
        }
        // gather x(t+1)
        if (t + 1 < LL) {
#pragma unroll
            for (int i = 0; i < 7; ++i) {
                const int k  = tid + i * NT;
                const int g  = k >> 8, dd = k & 255;
                const int grp = g0 + g;
                const int e  = (grp < B) ? g_order[grp * LL + t + 1] : -1;
                xh[g * OPW + dd] = (e >= 0) ? __float2half_rn(x[(size_t)e * DD + dd])
                                            : __half(0.f);
            }
        }
        __syncthreads();
    }

#pragma unroll
    for (int i = 0; i < 7; ++i) {
        const int grp = g0 + gb + 2 * i;
        if (grp < B) out[(size_t)grp * DD + d] = acc[i] * (1.0f / LL);
    }
}

// ---------------- entry point ----------------
extern "C" void kernel_launch(void* const* d_in, const int* in_sizes, int n_in,
                              void* d_out, int out_size) {
    const float* x     = (const float*)d_in[0];
    const float* ts    = (const float*)d_in[1];
    const float* wih0  = (const float*)d_in[2];
    const float* whh0  = (const float*)d_in[3];
    const float* bih0  = (const float*)d_in[4];
    const float* bhh0  = (const float*)d_in[5];
    const float* wih1  = (const float*)d_in[6];
    const float* whh1  = (const float*)d_in[7];
    const float* bih1  = (const float*)d_in[8];
    const float* bhh1  = (const float*)d_in[9];
    const int*   index = (const int*)d_in[10];
    float* out = (float*)d_out;

    const int E = in_sizes[0] / DD;
    const int B = out_size / DD;

    cudaFuncSetAttribute(gru_main, cudaFuncAttributeMaxDynamicSharedMemorySize, SMEM_TOT);

    // setup: [0,B) group sorts, [B, B+3072) fp16 weight blob pack
    setup_k<<<B + 3072, 256>>>(ts, index, E, B, wih0, whh0, wih1, whh1);

    int nb = (B + TG - 1) / TG;
    if (nb < 148) nb = 148;
    gru_main<<<nb, NT, SMEM_TOT>>>(x, bih0, bhh0, bih1, bhh1, out, B);
}

// round 11
// speedup vs baseline: 3.2606x; 1.2158x over previous
#include <cuda_runtime.h>
#include <cuda_fp16.h>
#include <cstdint>

#define DD 256        // feature/hidden dim
#define GD 768        // 3*DD gate dim
#define LL 96         // max group length
#define TG 14         // groups per block
#define BMAX 2048
#define NT 512        // 16 warps
#define KC16 16       // k16 chunks per K=256
#define PAIRB 49152   // bytes per pair-chunk (2 mats x 768 x 16 halves)
#define MATB 24576    // bytes per matrix within a pair
#define OPW 264       // halves per operand row (256 + 8 pad)

// ---- smem layout (bytes) ----
#define OFF_W    0                    // 3 stages x 49152 = 147456
#define OFF_XH   147456               // [16][OPW] half = 8448
#define OFF_H0H  155904
#define OFF_H1H  164352
#define OFF_SRZ  172800               // [512][TG] float = 28672 (r,z post-sigmoid)
#define OFF_SN   201472               // [256][TG] float = 14336 (n post-tanh)
#define OFF_CB   215808               // [2][768] float combined biases
#define OFF_HB   221952               // [2][256] float hh n-bias
#define SMEM_TOT 224000

typedef unsigned int u32;

// ---------------- device scratch ----------------
__device__ int    g_order[BMAX * LL];          // edge id per (group,t), -1 = pad
__device__ __half g_wblob[786432];             // [layer][pair16][mat][768][16] halves, swizzled

// ---------------- helpers ----------------
__device__ __forceinline__ float sigmoidf_(float v) {
    return __fdividef(1.f, 1.f + __expf(-v));
}
__device__ __forceinline__ float tanhf_(float v) {
    float t = __expf(2.f * v);
    return 1.f - __fdividef(2.f, t + 1.f);
}
__device__ __forceinline__ void cpc16(u32 dst, const void* src) {
    asm volatile("cp.async.cg.shared.global [%0], [%1], 16;\n" :: "r"(dst), "l"(src));
}
#define CPA_COMMIT() asm volatile("cp.async.commit_group;\n" ::)
#define CPA_WAIT1()  asm volatile("cp.async.wait_group 1;\n" ::: "memory")

__device__ __forceinline__ void ldsm_x4(u32& r0, u32& r1, u32& r2, u32& r3, u32 addr) {
    asm volatile("ldmatrix.sync.aligned.m8n8.x4.shared.b16 {%0,%1,%2,%3}, [%4];"
                 : "=r"(r0), "=r"(r1), "=r"(r2), "=r"(r3) : "r"(addr));
}
__device__ __forceinline__ void mma16(float* c, u32 a0, u32 a1, u32 a2, u32 a3,
                                      u32 b0, u32 b1) {
    asm volatile("mma.sync.aligned.m16n8k16.row.col.f32.f16.f16.f32 "
                 "{%0,%1,%2,%3}, {%4,%5,%6,%7}, {%8,%9}, {%0,%1,%2,%3};"
                 : "+f"(c[0]), "+f"(c[1]), "+f"(c[2]), "+f"(c[3])
                 : "r"(a0), "r"(a1), "r"(a2), "r"(a3), "r"(b0), "r"(b1));
}

// ---------------- fused setup: per-group timestamp sort + swizzled fp16 blob ----------------
__global__ void setup_k(const float* __restrict__ ts, const int* __restrict__ index,
                        int E, int B,
                        const float* __restrict__ wih0, const float* __restrict__ whh0,
                        const float* __restrict__ wih1, const float* __restrict__ whh1)
{
    const int b = blockIdx.x;
    if (b < B) {
        __shared__ int   lbub[2];
        __shared__ float sts[LL];
        const int i = threadIdx.x;
        if (i < 2) {
            const int key = b + i;
            int lo = 0, hi = E;
            while (lo < hi) {
                int m = (lo + hi) >> 1;
                if (index[m] < key) lo = m + 1; else hi = m;
            }
            lbub[i] = lo;
        }
        __syncthreads();
        const int off = lbub[0];
        const int c   = lbub[1] - lbub[0];
        if (i < c)  sts[i] = ts[off + i];
        if (i < LL) g_order[b * LL + i] = -1;
        __syncthreads();
        if (i < c) {
            const float ti = sts[i];
            int rank = 0;
            for (int j = 0; j < c; ++j) {
                float tj = sts[j];
                rank += (tj < ti || (tj == ti && j < i)) ? 1 : 0;
            }
            g_order[b * LL + (LL - c + rank)] = off + i;
        }
    } else {
        // blob: dst idx decomposed; swizzle baked: stored 16B-unit u_store holds
        // logical k8-unit u_log = u_store ^ ((row>>2)&1)
        int idx = (b - B) * 256 + threadIdx.x;       // 0 .. 786431
        if (idx < 786432) {
            int p   = idx / 393216;  int r1 = idx % 393216;
            int c   = r1 / 24576;    int r2 = r1 % 24576;
            int m   = r2 / 12288;    int r3 = r2 % 12288;
            int row = r3 / 16;       int hp = r3 % 16;
            int us  = hp >> 3;       int k8 = hp & 7;
            int ul  = us ^ ((row >> 2) & 1);
            int k   = c * 16 + ul * 8 + k8;
            const float* W = (p == 0) ? (m == 0 ? wih0 : whh0)
                                      : (m == 0 ? wih1 : whh1);
            g_wblob[idx] = __float2half_rn(W[row * DD + k]);
        }
    }
}

// ---------------- pair copy: 49152 B via 512 threads x 6 x 16B ----------------
__device__ __forceinline__ void issue_pair(const __half* __restrict__ wgl, int pair,
                                           u32 stage_u32, int tid) {
    const char* src = (const char*)(wgl + (size_t)pair * (PAIRB / 2)) + tid * 16;
    u32 dst = stage_u32 + tid * 16;
#pragma unroll
    for (int s = 0; s < 6; ++s) cpc16(dst + s * 8192, src + s * 8192);
}

// ---------------- one layer pass: gemm + publish(rz) + publish(n) ----------------
__device__ __forceinline__ void gemm_pass(
    const __half* __restrict__ wgl,     // this layer's blob base
    const __half* __restrict__ opA,     // [16][OPW] fp16 input operand
    const __half* __restrict__ opB,     // [16][OPW] fp16 hidden operand
    float* __restrict__ srz, float* __restrict__ sn,
    const float* __restrict__ cbl,      // [768] combined bias (r,z: ih+hh; n: ih)
    const float* __restrict__ hbl,      // [256] hh n-bias
    u32 wst_u32, int tid, int w, int lane)
{
    float cx[24], ch[24];
#pragma unroll
    for (int i = 0; i < 24; ++i) { cx[i] = 0.f; ch[i] = 0.f; }

    // prologue: pairs 0,1 -> stages 0,1
    issue_pair(wgl, 0, wst_u32, tid);             CPA_COMMIT();
    issue_pair(wgl, 1, wst_u32 + PAIRB, tid);     CPA_COMMIT();

    const int rowl  = lane & 15;
    const u32 thoff = (u32)(rowl * 32 + (((lane >> 4) ^ ((rowl >> 2) & 1)) * 16));
    const int bof   = (lane >> 2) * OPW + (lane & 3) * 2;    // half-index, n-tile 0

#pragma unroll 1
    for (int i = 0; i < KC16; ++i) {
        CPA_WAIT1();
        __syncthreads();
        if (i + 2 < KC16) issue_pair(wgl, i + 2, wst_u32 + ((i + 2) % 3) * PAIRB, tid);
        CPA_COMMIT();                               // always commit (keeps FIFO math)

        const u32 sbase = wst_u32 + (i % 3) * PAIRB;
        const int kh = i * 16;
        const u32 bx0 = *(const u32*)(opA + bof + kh);
        const u32 bx1 = *(const u32*)(opA + bof + kh + 8);
        const u32 by0 = *(const u32*)(opA + bof + 8 * OPW + kh);
        const u32 by1 = *(const u32*)(opA + bof + 8 * OPW + kh + 8);
        const u32 hx0 = *(const u32*)(opB + bof + kh);
        const u32 hx1 = *(const u32*)(opB + bof + kh + 8);
        const u32 hy0 = *(const u32*)(opB + bof + 8 * OPW + kh);
        const u32 hy1 = *(const u32*)(opB + bof + 8 * OPW + kh + 8);
#pragma unroll
        for (int j = 0; j < 3; ++j) {
            const u32 rowb = (u32)((w * 48 + j * 16) * 32) + thoff;
            u32 a0, a1, a2, a3;
            ldsm_x4(a0, a1, a2, a3, sbase + rowb);          // W_ih tile
            mma16(&cx[(j * 2 + 0) * 4], a0, a1, a2, a3, bx0, bx1);
            mma16(&cx[(j * 2 + 1) * 4], a0, a1, a2, a3, by0, by1);
            ldsm_x4(a0, a1, a2, a3, sbase + MATB + rowb);   // W_hh tile
            mma16(&ch[(j * 2 + 0) * 4], a0, a1, a2, a3, hx0, hx1);
            mma16(&ch[(j * 2 + 1) * 4], a0, a1, a2, a3, hy0, hy1);
        }
    }

    // ---- publish A: r,z -> sigmoid(srz); n-band: fold biases into regs ----
    const int r0  = lane >> 2;
    const int cp2 = (lane & 3) * 2;
#pragma unroll
    for (int j = 0; j < 3; ++j) {
        const int R = w * 48 + j * 16;
#pragma unroll
        for (int n = 0; n < 2; ++n) {
            const int col = n * 8 + cp2;
            float* cxp = &cx[(j * 2 + n) * 4];
            float* chp = &ch[(j * 2 + n) * 4];
            if (R < 512) {
                if (col < TG) {                      // col even -> col+1 <= 13
                    const int d0 = R + r0, d1 = d0 + 8;
                    float2 v0 = make_float2(sigmoidf_(cxp[0] + chp[0] + cbl[d0]),
                                            sigmoidf_(cxp[1] + chp[1] + cbl[d0]));
                    float2 v1 = make_float2(sigmoidf_(cxp[2] + chp[2] + cbl[d1]),
                                            sigmoidf_(cxp[3] + chp[3] + cbl[d1]));
                    *(float2*)&srz[d0 * TG + col] = v0;
                    *(float2*)&srz[d1 * TG + col] = v1;
                }
            } else {
                const int q0 = R - 512 + r0, q1 = q0 + 8;
                cxp[0] += cbl[512 + q0]; cxp[1] += cbl[512 + q0];
                cxp[2] += cbl[512 + q1]; cxp[3] += cbl[512 + q1];
                chp[0] += hbl[q0];       chp[1] += hbl[q0];
                chp[2] += hbl[q1];       chp[3] += hbl[q1];
            }
        }
    }
    __syncthreads();

    // ---- publish B: n = tanh(xn' + r*hn') (n-band warps only) ----
    if (w >= 10) {
#pragma unroll
        for (int j = 0; j < 3; ++j) {
            const int R = w * 48 + j * 16;
            if (R < 512) continue;
#pragma unroll
            for (int n = 0; n < 2; ++n) {
                const int col = n * 8 + cp2;
                if (col >= TG) continue;
                const float* cxp = &cx[(j * 2 + n) * 4];
                const float* chp = &ch[(j * 2 + n) * 4];
                const int q0 = R - 512 + r0, q1 = q0 + 8;
                float2 rv0 = *(const float2*)&srz[q0 * TG + col];
                float2 rv1 = *(const float2*)&srz[q1 * TG + col];
                float2 n0 = make_float2(tanhf_(cxp[0] + rv0.x * chp[0]),
                                        tanhf_(cxp[1] + rv0.y * chp[1]));
                float2 n1 = make_float2(tanhf_(cxp[2] + rv1.x * chp[2]),
                                        tanhf_(cxp[3] + rv1.y * chp[3]));
                *(float2*)&sn[q0 * TG + col] = n0;
                *(float2*)&sn[q1 * TG + col] = n1;
            }
        }
    }
    __syncthreads();
}

// ---------------- main persistent kernel ----------------
__global__ __launch_bounds__(NT, 1) void gru_main(
    const float* __restrict__ x,
    const float* __restrict__ bih0, const float* __restrict__ bhh0,
    const float* __restrict__ bih1, const float* __restrict__ bhh1,
    float* __restrict__ out, int B)
{
    extern __shared__ char sb[];
    __half* xh  = (__half*)(sb + OFF_XH);
    __half* h0h = (__half*)(sb + OFF_H0H);
    __half* h1h = (__half*)(sb + OFF_H1H);
    float*  srz = (float*)(sb + OFF_SRZ);
    float*  sn  = (float*)(sb + OFF_SN);
    float*  cb  = (float*)(sb + OFF_CB);
    float*  hb  = (float*)(sb + OFF_HB);
    const u32 wst_u32 = (u32)__cvta_generic_to_shared(sb + OFF_W);

    const int tid  = threadIdx.x;
    const int w    = tid >> 5;
    const int lane = tid & 31;
    const int d    = tid & 255;
    const int gb   = tid >> 8;          // 0 or 1
    const int g0   = blockIdx.x * TG;

    // biases -> smem
    for (int i = tid; i < GD; i += NT) {
        cb[i]       = (i < 512) ? bih0[i] + bhh0[i] : bih0[i];
        cb[GD + i]  = (i < 512) ? bih1[i] + bhh1[i] : bih1[i];
    }
    for (int i = tid; i < DD; i += NT) {
        hb[i]      = bhh0[512 + i];
        hb[DD + i] = bhh1[512 + i];
    }
    // zero operand halves (xh/h0h/h1h contiguous: 3*8448 B = 6336 u32)
    for (int i = tid; i < 6336; i += NT) ((u32*)xh)[i] = 0;
    __syncthreads();

    // gather x(0)
#pragma unroll
    for (int i = 0; i < 7; ++i) {
        const int k  = tid + i * NT;
        const int g  = k >> 8, dd = k & 255;
        const int grp = g0 + g;
        const int e  = (grp < B) ? g_order[grp * LL] : -1;
        xh[g * OPW + dd] = (e >= 0) ? __float2half_rn(x[(size_t)e * DD + dd]) : __half(0.f);
    }

    float h0r[7], h1r[7], acc[7];
#pragma unroll
    for (int i = 0; i < 7; ++i) { h0r[i] = 0.f; h1r[i] = 0.f; acc[i] = 0.f; }
    __syncthreads();

    const __half* wb0 = g_wblob;
    const __half* wb1 = g_wblob + 393216;

#pragma unroll 1
    for (int t = 0; t < LL; ++t) {
        // ---- layer 0 ----
        gemm_pass(wb0, xh, h0h, srz, sn, cb, hb, wst_u32, tid, w, lane);
#pragma unroll
        for (int i = 0; i < 7; ++i) {
            const int g = gb + 2 * i;
            float z = srz[(256 + d) * TG + g];
            float n = sn[d * TG + g];
            float h = h0r[i];
            float hn2 = n + z * (h - n);
            h0r[i] = hn2;
            h0h[g * OPW + d] = __float2half_rn(hn2);
        }
        // (ordering to layer-1 B-loads provided by gemm_pass's iter-0 barrier)

        // ---- layer 1 ----
        gemm_pass(wb1, h0h, h1h, srz, sn, cb + GD, hb + DD, wst_u32, tid, w, lane);
#pragma unroll
        for (int i = 0; i < 7; ++i) {
            const int g = gb + 2 * i;
            float z = srz[(256 + d) * TG + g];
            float n = sn[d * TG + g];
            float h = h1r[i];
            float hn2 = n + z * (h - n);
            h1r[i] = hn2;
            acc[i] += hn2;
            h1h[g * OPW + d] = __float2half_rn(hn2);
        }
        if (t + 1 < LL) {
#pragma unroll
            for (int i = 0; i < 7; ++i) {
                const int k  = tid + i * NT;
                const int g  = k >> 8, dd = k & 255;
                const int grp = g0 + g;
                const int e  = (grp < B) ? g_order[grp * LL + t + 1] : -1;
                xh[g * OPW + dd] = (e >= 0) ? __float2half_rn(x[(size_t)e * DD + dd])
                                            : __half(0.f);
            }
        }
    }

#pragma unroll
    for (int i = 0; i < 7; ++i) {
        const int grp = g0 + gb + 2 * i;
        if (grp < B) out[(size_t)grp * DD + d] = acc[i] * (1.0f / LL);
    }
}

// ---------------- entry point ----------------
extern "C" void kernel_launch(void* const* d_in, const int* in_sizes, int n_in,
                              void* d_out, int out_size) {
    const float* x     = (const float*)d_in[0];
    const float* ts    = (const float*)d_in[1];
    const float* wih0  = (const float*)d_in[2];
    const float* whh0  = (const float*)d_in[3];
    const float* bih0  = (const float*)d_in[4];
    const float* bhh0  = (const float*)d_in[5];
    const float* wih1  = (const float*)d_in[6];
    const float* whh1  = (const float*)d_in[7];
    const float* bih1  = (const float*)d_in[8];
    const float* bhh1  = (const float*)d_in[9];
    const int*   index = (const int*)d_in[10];
    float* out = (float*)d_out;

    const int E = in_sizes[0] / DD;
    const int B = out_size / DD;

    cudaFuncSetAttribute(gru_main, cudaFuncAttributeMaxDynamicSharedMemorySize, SMEM_TOT);

    // setup: [0,B) group sorts, [B, B+3072) swizzled fp16 weight blob
    setup_k<<<B + 3072, 256>>>(ts, index, E, B, wih0, whh0, wih1, whh1);

    int nb = (B + TG - 1) / TG;
    if (nb < 148) nb = 148;
    gru_main<<<nb, NT, SMEM_TOT>>>(x, bih0, bhh0, bih1, bhh1, out, B);
}

// round 12
// speedup vs baseline: 4.1927x; 1.2859x over previous
#include <cuda_runtime.h>
#include <cuda_fp16.h>
#include <cstdint>

#define DD 256        // feature/hidden dim
#define GD 768        // 3*DD gate dim
#define LL 96         // max group length
#define TG 14         // groups per block
#define BMAX 2048
#define NT 512        // 16 warps
#define KC16 16       // k16 chunks per K=256
#define WCHUNK 3072   // bytes per warp-chunk (2 mats x 48 rows x 16 halves)
#define WSTAGES 9216  // 3 stages x 3072 per warp
#define OPW 264       // halves per operand row (256 + 8 pad)

// ---- smem layout (bytes) ----
#define OFF_W    0                    // [16 warps][3 stages][3072] = 147456
#define OFF_XH   147456               // [16][OPW] half = 8448
#define OFF_H0H  155904
#define OFF_H1H  164352
#define OFF_SRZ  172800               // [512][TG] float = 28672 (r,z post-sigmoid)
#define OFF_SN   201472               // [256][TG] float = 14336 (n post-tanh)
#define OFF_CB   215808               // [2][768] float combined biases
#define OFF_HB   221952               // [2][256] float hh n-bias
#define SMEM_TOT 224000

typedef unsigned int u32;

// ---------------- device scratch ----------------
__device__ int    g_order[BMAX * LL];   // edge id per (group,t), -1 = pad
// blob: [layer][warp][chunk][mat][row48][16 halves], k-swizzle baked
__device__ __half g_wblob[786432];

// ---------------- helpers ----------------
__device__ __forceinline__ float sigmoidf_(float v) {
    return __fdividef(1.f, 1.f + __expf(-v));
}
__device__ __forceinline__ float tanhf_(float v) {
    float t = __expf(2.f * v);
    return 1.f - __fdividef(2.f, t + 1.f);
}
__device__ __forceinline__ void cpc16(u32 dst, const void* src) {
    asm volatile("cp.async.cg.shared.global [%0], [%1], 16;\n" :: "r"(dst), "l"(src));
}
#define CPA_COMMIT() asm volatile("cp.async.commit_group;\n" ::)
#define CPA_WAIT1()  asm volatile("cp.async.wait_group 1;\n" ::: "memory")

__device__ __forceinline__ void ldsm_x4(u32& r0, u32& r1, u32& r2, u32& r3, u32 addr) {
    asm volatile("ldmatrix.sync.aligned.m8n8.x4.shared.b16 {%0,%1,%2,%3}, [%4];"
                 : "=r"(r0), "=r"(r1), "=r"(r2), "=r"(r3) : "r"(addr));
}
__device__ __forceinline__ void mma16(float* c, u32 a0, u32 a1, u32 a2, u32 a3,
                                      u32 b0, u32 b1) {
    asm volatile("mma.sync.aligned.m16n8k16.row.col.f32.f16.f16.f32 "
                 "{%0,%1,%2,%3}, {%4,%5,%6,%7}, {%8,%9}, {%0,%1,%2,%3};"
                 : "+f"(c[0]), "+f"(c[1]), "+f"(c[2]), "+f"(c[3])
                 : "r"(a0), "r"(a1), "r"(a2), "r"(a3), "r"(b0), "r"(b1));
}

// ---------------- fused setup: per-group timestamp sort + per-warp fp16 blob ----------------
__global__ void setup_k(const float* __restrict__ ts, const int* __restrict__ index,
                        int E, int B,
                        const float* __restrict__ wih0, const float* __restrict__ whh0,
                        const float* __restrict__ wih1, const float* __restrict__ whh1)
{
    const int b = blockIdx.x;
    if (b < B) {
        __shared__ int   lbub[2];
        __shared__ float sts[LL];
        const int i = threadIdx.x;
        if (i < 2) {
            const int key = b + i;
            int lo = 0, hi = E;
            while (lo < hi) {
                int m = (lo + hi) >> 1;
                if (index[m] < key) lo = m + 1; else hi = m;
            }
            lbub[i] = lo;
        }
        __syncthreads();
        const int off = lbub[0];
        const int c   = lbub[1] - lbub[0];
        if (i < c)  sts[i] = ts[off + i];
        if (i < LL) g_order[b * LL + i] = -1;
        __syncthreads();
        if (i < c) {
            const float ti = sts[i];
            int rank = 0;
            for (int j = 0; j < c; ++j) {
                float tj = sts[j];
                rank += (tj < ti || (tj == ti && j < i)) ? 1 : 0;
            }
            g_order[b * LL + (LL - c + rank)] = off + i;
        }
    } else {
        // dst-indexed pack into per-warp-contiguous swizzled blob
        int idx = (b - B) * 256 + threadIdx.x;       // 0 .. 786431
        if (idx < 786432) {
            int p   = idx / 393216;  int r1 = idx % 393216;
            int wp  = r1 / 24576;    int r2 = r1 % 24576;    // warp 0..15
            int c   = r2 / 1536;     int r3 = r2 % 1536;     // chunk 0..15
            int m   = r3 / 768;      int r4 = r3 % 768;      // mat 0..1
            int row48 = r4 / 16;     int hp = r4 % 16;
            int us  = hp >> 3;       int k8 = hp & 7;
            int ul  = us ^ ((row48 >> 2) & 1);               // baked XOR swizzle
            int k   = c * 16 + ul * 8 + k8;
            int row = wp * 48 + row48;
            const float* W = (p == 0) ? (m == 0 ? wih0 : whh0)
                                      : (m == 0 ? wih1 : whh1);
            g_wblob[idx] = __float2half_rn(W[row * DD + k]);
        }
    }
}

// ---------------- per-warp chunk copy: 3072 B = 32 lanes x 6 x 16B ----------------
__device__ __forceinline__ void issue_chunk(const char* __restrict__ wsrc, int c,
                                            u32 wstw, int stage, int loff) {
    const char* s = wsrc + c * WCHUNK + loff;
    u32 dst = wstw + stage * WCHUNK + loff;
#pragma unroll
    for (int q = 0; q < 6; ++q) cpc16(dst + q * 512, s + q * 512);
}

// ---------------- one layer pass: per-warp streamed gemm + publish ----------------
__device__ __forceinline__ void gemm_pass(
    const char* __restrict__ wsrc,      // this layer+warp's blob base (bytes)
    const __half* __restrict__ opA,     // [16][OPW] fp16 input operand
    const __half* __restrict__ opB,     // [16][OPW] fp16 hidden operand
    float* __restrict__ srz, float* __restrict__ sn,
    const float* __restrict__ cbl,      // [768] combined bias (r,z: ih+hh; n: ih)
    const float* __restrict__ hbl,      // [256] hh n-bias
    u32 wstw, int w, int lane)
{
    float cx[24], ch[24];
#pragma unroll
    for (int i = 0; i < 24; ++i) { cx[i] = 0.f; ch[i] = 0.f; }

    const int loff = lane * 16;
    // prologue: chunks 0,1 -> stages 0,1
    issue_chunk(wsrc, 0, wstw, 0, loff); CPA_COMMIT();
    issue_chunk(wsrc, 1, wstw, 1, loff); CPA_COMMIT();

    const int rowl  = lane & 15;
    const u32 axor  = (u32)((((lane >> 4) ^ ((rowl >> 2) & 1))) * 16);
    const int bof   = (lane >> 2) * OPW + (lane & 3) * 2;

#pragma unroll 1
    for (int i = 0; i < KC16; ++i) {
        if (i + 2 < KC16) issue_chunk(wsrc, i + 2, wstw, (i + 2) % 3, loff);
        CPA_COMMIT();                       // always commit (FIFO arithmetic)
        CPA_WAIT1();                        // chunk i landed

        const u32 sbase = wstw + (i % 3) * WCHUNK;
        const int kh = i * 16;
        const u32 bx0 = *(const u32*)(opA + bof + kh);
        const u32 bx1 = *(const u32*)(opA + bof + kh + 8);
        const u32 by0 = *(const u32*)(opA + bof + 8 * OPW + kh);
        const u32 by1 = *(const u32*)(opA + bof + 8 * OPW + kh + 8);
        const u32 hx0 = *(const u32*)(opB + bof + kh);
        const u32 hx1 = *(const u32*)(opB + bof + kh + 8);
        const u32 hy0 = *(const u32*)(opB + bof + 8 * OPW + kh);
        const u32 hy1 = *(const u32*)(opB + bof + 8 * OPW + kh + 8);
#pragma unroll
        for (int j = 0; j < 3; ++j) {
            const u32 ra = sbase + (u32)((j * 16 + rowl) * 32) + axor;
            u32 a0, a1, a2, a3;
            ldsm_x4(a0, a1, a2, a3, ra);            // W_ih rows (mat 0)
            mma16(&cx[(j * 2 + 0) * 4], a0, a1, a2, a3, bx0, bx1);
            mma16(&cx[(j * 2 + 1) * 4], a0, a1, a2, a3, by0, by1);
            ldsm_x4(a0, a1, a2, a3, ra + 1536);     // W_hh rows (mat 1)
            mma16(&ch[(j * 2 + 0) * 4], a0, a1, a2, a3, hx0, hx1);
            mma16(&ch[(j * 2 + 1) * 4], a0, a1, a2, a3, hy0, hy1);
        }
    }

    // ---- publish A: r,z -> sigmoid(srz); n-band: fold biases into regs ----
    const int r0  = lane >> 2;
    const int cp2 = (lane & 3) * 2;
#pragma unroll
    for (int j = 0; j < 3; ++j) {
        const int R = w * 48 + j * 16;
#pragma unroll
        for (int n = 0; n < 2; ++n) {
            const int col = n * 8 + cp2;
            float* cxp = &cx[(j * 2 + n) * 4];
            float* chp = &ch[(j * 2 + n) * 4];
            if (R < 512) {
                if (col < TG) {
                    const int d0 = R + r0, d1 = d0 + 8;
                    float2 v0 = make_float2(sigmoidf_(cxp[0] + chp[0] + cbl[d0]),
                                            sigmoidf_(cxp[1] + chp[1] + cbl[d0]));
                    float2 v1 = make_float2(sigmoidf_(cxp[2] + chp[2] + cbl[d1]),
                                            sigmoidf_(cxp[3] + chp[3] + cbl[d1]));
                    *(float2*)&srz[d0 * TG + col] = v0;
                    *(float2*)&srz[d1 * TG + col] = v1;
                }
            } else {
                const int q0 = R - 512 + r0, q1 = q0 + 8;
                cxp[0] += cbl[512 + q0]; cxp[1] += cbl[512 + q0];
                cxp[2] += cbl[512 + q1]; cxp[3] += cbl[512 + q1];
                chp[0] += hbl[q0];       chp[1] += hbl[q0];
                chp[2] += hbl[q1];       chp[3] += hbl[q1];
            }
        }
    }
    __syncthreads();

    // ---- publish B: n = tanh(xn' + r*hn') (n-band warps only) ----
    if (w >= 10) {
#pragma unroll
        for (int j = 0; j < 3; ++j) {
            const int R = w * 48 + j * 16;
            if (R < 512) continue;
#pragma unroll
            for (int n = 0; n < 2; ++n) {
                const int col = n * 8 + cp2;
                if (col >= TG) continue;
                const float* cxp = &cx[(j * 2 + n) * 4];
                const float* chp = &ch[(j * 2 + n) * 4];
                const int q0 = R - 512 + r0, q1 = q0 + 8;
                float2 rv0 = *(const float2*)&srz[q0 * TG + col];
                float2 rv1 = *(const float2*)&srz[q1 * TG + col];
                float2 n0 = make_float2(tanhf_(cxp[0] + rv0.x * chp[0]),
                                        tanhf_(cxp[1] + rv0.y * chp[1]));
                float2 n1 = make_float2(tanhf_(cxp[2] + rv1.x * chp[2]),
                                        tanhf_(cxp[3] + rv1.y * chp[3]));
                *(float2*)&sn[q0 * TG + col] = n0;
                *(float2*)&sn[q1 * TG + col] = n1;
            }
        }
    }
    __syncthreads();
}

// ---------------- main persistent kernel ----------------
__global__ __launch_bounds__(NT, 1) void gru_main(
    const float* __restrict__ x,
    const float* __restrict__ bih0, const float* __restrict__ bhh0,
    const float* __restrict__ bih1, const float* __restrict__ bhh1,
    float* __restrict__ out, int B)
{
    extern __shared__ char sb[];
    __half* xh  = (__half*)(sb + OFF_XH);
    __half* h0h = (__half*)(sb + OFF_H0H);
    __half* h1h = (__half*)(sb + OFF_H1H);
    float*  srz = (float*)(sb + OFF_SRZ);
    float*  sn  = (float*)(sb + OFF_SN);
    float*  cb  = (float*)(sb + OFF_CB);
    float*  hb  = (float*)(sb + OFF_HB);

    const int tid  = threadIdx.x;
    const int w    = tid >> 5;
    const int lane = tid & 31;
    const int d    = tid & 255;
    const int gb   = tid >> 8;          // 0 or 1
    const int g0   = blockIdx.x * TG;

    const u32 wstw = (u32)__cvta_generic_to_shared(sb + OFF_W) + (u32)(w * WSTAGES);
    const char* wb0w = (const char*)(g_wblob)          + (size_t)w * 49152;
    const char* wb1w = (const char*)(g_wblob + 393216) + (size_t)w * 49152;

    // biases -> smem
    for (int i = tid; i < GD; i += NT) {
        cb[i]       = (i < 512) ? bih0[i] + bhh0[i] : bih0[i];
        cb[GD + i]  = (i < 512) ? bih1[i] + bhh1[i] : bih1[i];
    }
    for (int i = tid; i < DD; i += NT) {
        hb[i]      = bhh0[512 + i];
        hb[DD + i] = bhh1[512 + i];
    }
    // zero operand halves (xh/h0h/h1h contiguous: 3*8448 B = 6336 u32)
    for (int i = tid; i < 6336; i += NT) ((u32*)xh)[i] = 0;
    __syncthreads();

    // gather x(0)
#pragma unroll
    for (int i = 0; i < 7; ++i) {
        const int k  = tid + i * NT;
        const int g  = k >> 8, dd = k & 255;
        const int grp = g0 + g;
        const int e  = (grp < B) ? g_order[grp * LL] : -1;
        xh[g * OPW + dd] = (e >= 0) ? __float2half_rn(x[(size_t)e * DD + dd]) : __half(0.f);
    }

    float h0r[7], h1r[7], acc[7];
#pragma unroll
    for (int i = 0; i < 7; ++i) { h0r[i] = 0.f; h1r[i] = 0.f; acc[i] = 0.f; }
    __syncthreads();

#pragma unroll 1
    for (int t = 0; t < LL; ++t) {
        // ---- layer 0 ----
        gemm_pass(wb0w, xh, h0h, srz, sn, cb, hb, wstw, w, lane);
#pragma unroll
        for (int i = 0; i < 7; ++i) {
            const int g = gb + 2 * i;
            float z = srz[(256 + d) * TG + g];
            float n = sn[d * TG + g];
            float h = h0r[i];
            float hn2 = n + z * (h - n);
            h0r[i] = hn2;
            h0h[g * OPW + d] = __float2half_rn(hn2);
        }
        __syncthreads();    // h0h stable before layer-1 B loads

        // ---- layer 1 ----
        gemm_pass(wb1w, h0h, h1h, srz, sn, cb + GD, hb + DD, wstw, w, lane);
#pragma unroll
        for (int i = 0; i < 7; ++i) {
            const int g = gb + 2 * i;
            float z = srz[(256 + d) * TG + g];
            float n = sn[d * TG + g];
            float h = h1r[i];
            float hn2 = n + z * (h - n);
            h1r[i] = hn2;
            acc[i] += hn2;
            h1h[g * OPW + d] = __float2half_rn(hn2);
        }
        if (t + 1 < LL) {
#pragma unroll
            for (int i = 0; i < 7; ++i) {
                const int k  = tid + i * NT;
                const int g  = k >> 8, dd = k & 255;
                const int grp = g0 + g;
                const int e  = (grp < B) ? g_order[grp * LL + t + 1] : -1;
                xh[g * OPW + dd] = (e >= 0) ? __float2half_rn(x[(size_t)e * DD + dd])
                                            : __half(0.f);
            }
        }
        __syncthreads();    // xh/h1h stable before next step's gemm reads
    }

#pragma unroll
    for (int i = 0; i < 7; ++i) {
        const int grp = g0 + gb + 2 * i;
        if (grp < B) out[(size_t)grp * DD + d] = acc[i] * (1.0f / LL);
    }
}

// ---------------- entry point ----------------
extern "C" void kernel_launch(void* const* d_in, const int* in_sizes, int n_in,
                              void* d_out, int out_size) {
    const float* x     = (const float*)d_in[0];
    const float* ts    = (const float*)d_in[1];
    const float* wih0  = (const float*)d_in[2];
    const float* whh0  = (const float*)d_in[3];
    const float* bih0  = (const float*)d_in[4];
    const float* bhh0  = (const float*)d_in[5];
    const float* wih1  = (const float*)d_in[6];
    const float* whh1  = (const float*)d_in[7];
    const float* bih1  = (const float*)d_in[8];
    const float* bhh1  = (const float*)d_in[9];
    const int*   index = (const int*)d_in[10];
    float* out = (float*)d_out;

    const int E = in_sizes[0] / DD;
    const int B = out_size / DD;

    cudaFuncSetAttribute(gru_main, cudaFuncAttributeMaxDynamicSharedMemorySize, SMEM_TOT);

    // setup: [0,B) group sorts, [B, B+3072) per-warp swizzled fp16 blob
    setup_k<<<B + 3072, 256>>>(ts, index, E, B, wih0, whh0, wih1, whh1);

    int nb = (B + TG - 1) / TG;
    if (nb < 148) nb = 148;
    gru_main<<<nb, NT, SMEM_TOT>>>(x, bih0, bhh0, bih1, bhh1, out, B);
}

// round 13
// speedup vs baseline: 4.5066x; 1.0749x over previous
#include <cuda_runtime.h>
#include <cuda_fp16.h>
#include <cstdint>

#define DD 256        // feature/hidden dim
#define GD 768        // 3*DD gate dim
#define LL 96         // max group length
#define TG 14         // groups per block
#define BMAX 2048
#define NT 512        // 16 warps
#define WCHUNK 3072   // bytes per warp-chunk (ring stage size)
#define WSTAGES 9216  // 3 stages x 3072 per warp
#define OPW 264       // halves per h-operand row (256 + 8 pad)
#define XPW 776       // halves per xp row (768 + 8 pad)

// ---- main-kernel smem layout (bytes) ----
#define OFF_W    0                    // [16 warps][3 stages][3072] = 147456
#define OFF_XPS  147456               // [16][XPW] half = 24832
#define OFF_H0H  172288               // [16][OPW] half = 8448
#define OFF_H1H  180736               // 8448
#define OFF_SRZ  189184               // [512][TG] half = 14336 (r,z post-sigmoid)
#define OFF_SN   203520               // [256][TG] half = 7168  (n post-tanh)
#define OFF_CB   210688               // [2][768] float combined biases
#define OFF_HB   216832               // [2][256] float hh n-bias
#define SMEM_TOT 218880

// ---- xp precompute kernel smem ----
#define XSTG     1536                 // per-warp stage bytes (1 matrix, k16)
#define XP_RING  73728                // 16 x 3 x 1536
#define XP_SMEM  (XP_RING + 64 * OPW * 2)   // + x tile [64][OPW] half

typedef unsigned int u32;

// ---------------- device scratch ----------------
__device__ int    g_order[BMAX * LL];   // edge id per (group,t), -1 = pad
// blob A: [layer][warp][chunk16][mat][row48][16h], k16 XOR swizzle baked
__device__ __half g_wblob[786432];
// blob B: W_hh0 [warp][chunk8(k32)][row48][4 units x 8h], k32 XOR swizzle baked
__device__ __half g_whh0[196608];
// precomputed xp = W_ih0 @ x  (no bias), [e][768] fp16
__device__ __half g_xp[(size_t)BMAX * LL * GD];

// ---------------- helpers ----------------
__device__ __forceinline__ float sigmoidf_(float v) {
    return __fdividef(1.f, 1.f + __expf(-v));
}
__device__ __forceinline__ float tanhf_(float v) {
    float t = __expf(2.f * v);
    return 1.f - __fdividef(2.f, t + 1.f);
}
__device__ __forceinline__ void cpc16(u32 dst, const void* src) {
    asm volatile("cp.async.cg.shared.global [%0], [%1], 16;\n" :: "r"(dst), "l"(src));
}
#define CPA_COMMIT() asm volatile("cp.async.commit_group;\n" ::)
#define CPA_WAIT2()  asm volatile("cp.async.wait_group 2;\n" ::: "memory")

__device__ __forceinline__ void ldsm_x4(u32& r0, u32& r1, u32& r2, u32& r3, u32 addr) {
    asm volatile("ldmatrix.sync.aligned.m8n8.x4.shared.b16 {%0,%1,%2,%3}, [%4];"
                 : "=r"(r0), "=r"(r1), "=r"(r2), "=r"(r3) : "r"(addr));
}
__device__ __forceinline__ void mma16(float* c, u32 a0, u32 a1, u32 a2, u32 a3,
                                      u32 b0, u32 b1) {
    asm volatile("mma.sync.aligned.m16n8k16.row.col.f32.f16.f16.f32 "
                 "{%0,%1,%2,%3}, {%4,%5,%6,%7}, {%8,%9}, {%0,%1,%2,%3};"
                 : "+f"(c[0]), "+f"(c[1]), "+f"(c[2]), "+f"(c[3])
                 : "r"(a0), "r"(a1), "r"(a2), "r"(a3), "r"(b0), "r"(b1));
}

// ---------------- fused setup: group sort + both weight blobs ----------------
__global__ void setup_k(const float* __restrict__ ts, const int* __restrict__ index,
                        int E, int B,
                        const float* __restrict__ wih0, const float* __restrict__ whh0,
                        const float* __restrict__ wih1, const float* __restrict__ whh1)
{
    const int b = blockIdx.x;
    if (b < B) {
        __shared__ int   lbub[2];
        __shared__ float sts[LL];
        const int i = threadIdx.x;
        if (i < 2) {
            const int key = b + i;
            int lo = 0, hi = E;
            while (lo < hi) {
                int m = (lo + hi) >> 1;
                if (index[m] < key) lo = m + 1; else hi = m;
            }
            lbub[i] = lo;
        }
        __syncthreads();
        const int off = lbub[0];
        const int c   = lbub[1] - lbub[0];
        if (i < c)  sts[i] = ts[off + i];
        if (i < LL) g_order[b * LL + i] = -1;
        __syncthreads();
        if (i < c) {
            const float ti = sts[i];
            int rank = 0;
            for (int j = 0; j < c; ++j) {
                float tj = sts[j];
                rank += (tj < ti || (tj == ti && j < i)) ? 1 : 0;
            }
            g_order[b * LL + (LL - c + rank)] = off + i;
        }
    } else {
        int idx = (b - B) * 256 + threadIdx.x;       // 0 .. 983039
        if (idx < 786432) {
            // blob A (k16 pairs, per-warp): both layers
            int p   = idx / 393216;  int r1 = idx % 393216;
            int wp  = r1 / 24576;    int r2 = r1 % 24576;
            int c   = r2 / 1536;     int r3 = r2 % 1536;
            int m   = r3 / 768;      int r4 = r3 % 768;
            int row48 = r4 / 16;     int hp = r4 % 16;
            int us  = hp >> 3;       int k8 = hp & 7;
            int ul  = us ^ ((row48 >> 2) & 1);
            int k   = c * 16 + ul * 8 + k8;
            int row = wp * 48 + row48;
            const float* W = (p == 0) ? (m == 0 ? wih0 : whh0)
                                      : (m == 0 ? wih1 : whh1);
            g_wblob[idx] = __float2half_rn(W[row * DD + k]);
        } else if (idx < 983040) {
            // blob B: W_hh0 in per-warp k32 layout
            int i2 = idx - 786432;                   // 0 .. 196607
            int wp = i2 / 12288;     int r1 = i2 % 12288;
            int c  = r1 / 1536;      int r2 = r1 % 1536;
            int row48 = r2 / 32;     int hp = r2 % 32;
            int us = hp >> 3;        int k8 = hp & 7;
            int ul = us ^ ((row48 >> 1) & 3);
            int k  = c * 32 + ul * 8 + k8;
            int row = wp * 48 + row48;
            g_whh0[i2] = __float2half_rn(whh0[row * DD + k]);
        }
    }
}

// ---------------- xp precompute: xp[e][768] = W_ih0 @ x[e] (fp16 out) ----------------
__global__ __launch_bounds__(NT, 1) void xp_k(const float* __restrict__ x, int E)
{
    extern __shared__ char sb[];
    __half* xt = (__half*)(sb + XP_RING);            // [64][OPW]
    const int tid  = threadIdx.x;
    const int w    = tid >> 5;
    const int lane = tid & 31;
    const int e0   = blockIdx.x * 64;

    const u32 wstw = (u32)__cvta_generic_to_shared(sb) + (u32)(w * 3 * XSTG);
    const char* wsrc = (const char*)g_wblob + (size_t)w * 49152;   // layer0, warp w

    // stage x tile (fp32 -> fp16), zero-pad rows beyond E
    for (int idx = tid; idx < 64 * DD; idx += NT) {
        const int r = idx >> 8, c = idx & 255;
        const int e = e0 + r;
        xt[r * OPW + c] = (e < E) ? __float2half_rn(x[(size_t)e * DD + c]) : __half(0.f);
    }
    __syncthreads();

    float acc[96];
#pragma unroll
    for (int i = 0; i < 96; ++i) acc[i] = 0.f;

    const int loff = lane * 16;
    // prologue: chunks 0,1 (mat0 halves of blob-A chunks: first 1536 B)
    {
        const char* s0 = wsrc + 0 * WCHUNK + loff;
        const char* s1 = wsrc + 1 * WCHUNK + loff;
        u32 d0 = wstw + 0 * XSTG + loff, d1 = wstw + 1 * XSTG + loff;
        cpc16(d0, s0); cpc16(d0 + 512, s0 + 512); cpc16(d0 + 1024, s0 + 1024);
        CPA_COMMIT();
        cpc16(d1, s1); cpc16(d1 + 512, s1 + 512); cpc16(d1 + 1024, s1 + 1024);
        CPA_COMMIT();
    }

    const int rowl = lane & 15;
    const u32 axor = (u32)((((lane >> 4) ^ ((rowl >> 2) & 1))) * 16);

#pragma unroll 1
    for (int i = 0; i < 16; ++i) {
        if (i + 2 < 16) {
            const char* s = wsrc + (i + 2) * WCHUNK + loff;
            u32 d = wstw + ((i + 2) % 3) * XSTG + loff;
            cpc16(d, s); cpc16(d + 512, s + 512); cpc16(d + 1024, s + 1024);
        }
        CPA_COMMIT();
        CPA_WAIT2();
        const u32 sbase = wstw + (i % 3) * XSTG;
        const int kh = i * 16;
        u32 a[3][4];
#pragma unroll
        for (int j = 0; j < 3; ++j)
            ldsm_x4(a[j][0], a[j][1], a[j][2], a[j][3],
                    sbase + (u32)((j * 16 + rowl) * 32) + axor);
#pragma unroll
        for (int nt = 0; nt < 8; ++nt) {
            const int brow = (nt * 8 + (lane >> 2)) * OPW + (lane & 3) * 2 + kh;
            const u32 b0 = *(const u32*)(xt + brow);
            const u32 b1 = *(const u32*)(xt + brow + 8);
#pragma unroll
            for (int j = 0; j < 3; ++j)
                mma16(&acc[(j * 8 + nt) * 4], a[j][0], a[j][1], a[j][2], a[j][3], b0, b1);
        }
    }

    // scatter results
    const int r0 = lane >> 2, cp2 = (lane & 3) * 2;
#pragma unroll
    for (int j = 0; j < 3; ++j) {
        const int d0 = w * 48 + j * 16 + r0;
#pragma unroll
        for (int nt = 0; nt < 8; ++nt) {
            const int e = e0 + nt * 8 + cp2;
            const float* c = &acc[(j * 8 + nt) * 4];
            if (e < E) {
                g_xp[(size_t)e * GD + d0]     = __float2half_rn(c[0]);
                g_xp[(size_t)e * GD + d0 + 8] = __float2half_rn(c[2]);
            }
            if (e + 1 < E) {
                g_xp[(size_t)(e + 1) * GD + d0]     = __float2half_rn(c[1]);
                g_xp[(size_t)(e + 1) * GD + d0 + 8] = __float2half_rn(c[3]);
            }
        }
    }
}

// ---------------- per-warp 3072B chunk copy ----------------
__device__ __forceinline__ void issue_chunk(const char* __restrict__ wsrc, int c,
                                            u32 wstw, int stage, int loff) {
    const char* s = wsrc + c * WCHUNK + loff;
    u32 dst = wstw + stage * WCHUNK + loff;
#pragma unroll
    for (int q = 0; q < 6; ++q) cpc16(dst + q * 512, s + q * 512);
}

// ---------------- layer-0 pass: hh GEMM only (k32 chunks) + publish ----------------
__device__ __forceinline__ void gemm_pass0(
    const char* __restrict__ wsrc,      // g_whh0 + warp base
    const __half* __restrict__ opB,     // h0 operand [16][OPW]
    const __half* __restrict__ xps,     // [16][XPW] staged xp
    __half* __restrict__ srz, __half* __restrict__ sn,
    const float* __restrict__ cbl, const float* __restrict__ hbl,
    u32 wstw, int w, int lane)
{
    float ch[24];
#pragma unroll
    for (int i = 0; i < 24; ++i) ch[i] = 0.f;

    const int loff = lane * 16;
    issue_chunk(wsrc, 0, wstw, 0, loff); CPA_COMMIT();
    issue_chunk(wsrc, 1, wstw, 1, loff); CPA_COMMIT();

    const int rowl = lane & 15;
    const int ksel = lane >> 4;
    const int bof  = (lane >> 2) * OPW + (lane & 3) * 2;

#pragma unroll 1
    for (int i = 0; i < 8; ++i) {
        if (i + 2 < 8) issue_chunk(wsrc, i + 2, wstw, (i + 2) % 3, loff);
        CPA_COMMIT();
        CPA_WAIT2();
        const u32 sbase = wstw + (i % 3) * WCHUNK;
        const int kh = i * 32;
        u32 hx[4], hy[4];
#pragma unroll
        for (int q = 0; q < 4; ++q) {
            hx[q] = *(const u32*)(opB + bof + kh + q * 8);
            hy[q] = *(const u32*)(opB + bof + 8 * OPW + kh + q * 8);
        }
#pragma unroll
        for (int j = 0; j < 3; ++j) {
            const int row = j * 16 + rowl;
            const u32 rb  = sbase + (u32)(row * 64);
            const u32 sw  = (u32)(((row >> 1) & 3) * 16);
#pragma unroll
            for (int kk = 0; kk < 2; ++kk) {
                u32 a0, a1, a2, a3;
                const u32 addr = rb + (((u32)((kk * 2 + ksel) * 16)) ^ sw);
                ldsm_x4(a0, a1, a2, a3, addr);
                mma16(&ch[(j * 2 + 0) * 4], a0, a1, a2, a3, hx[kk * 2], hx[kk * 2 + 1]);
                mma16(&ch[(j * 2 + 1) * 4], a0, a1, a2, a3, hy[kk * 2], hy[kk * 2 + 1]);
            }
        }
    }

    // publish A: r,z = sigmoid(xp + hh + cb); n-band: fold xp + biases into regs
    const int r0 = lane >> 2, cp2 = (lane & 3) * 2;
    float cx[24];
#pragma unroll
    for (int j = 0; j < 3; ++j) {
        const int R = w * 48 + j * 16;
#pragma unroll
        for (int n = 0; n < 2; ++n) {
            const int col = n * 8 + cp2;
            float* chp = &ch[(j * 2 + n) * 4];
            float* cxp = &cx[(j * 2 + n) * 4];
            if (R < 512) {
                if (col < TG) {
                    const int d0 = R + r0, d1 = d0 + 8;
                    float x00 = __half2float(xps[col * XPW + d0]);
                    float x01 = __half2float(xps[(col + 1) * XPW + d0]);
                    float x10 = __half2float(xps[col * XPW + d1]);
                    float x11 = __half2float(xps[(col + 1) * XPW + d1]);
                    *(__half2*)&srz[d0 * TG + col] =
                        __floats2half2_rn(sigmoidf_(x00 + chp[0] + cbl[d0]),
                                          sigmoidf_(x01 + chp[1] + cbl[d0]));
                    *(__half2*)&srz[d1 * TG + col] =
                        __floats2half2_rn(sigmoidf_(x10 + chp[2] + cbl[d1]),
                                          sigmoidf_(x11 + chp[3] + cbl[d1]));
                }
            } else {
                const int q0 = R - 512 + r0, q1 = q0 + 8;
                cxp[0] = __half2float(xps[col * XPW + 512 + q0]) + cbl[512 + q0];
                cxp[1] = __half2float(xps[(col + 1) * XPW + 512 + q0]) + cbl[512 + q0];
                cxp[2] = __half2float(xps[col * XPW + 512 + q1]) + cbl[512 + q1];
                cxp[3] = __half2float(xps[(col + 1) * XPW + 512 + q1]) + cbl[512 + q1];
                chp[0] += hbl[q0]; chp[1] += hbl[q0];
                chp[2] += hbl[q1]; chp[3] += hbl[q1];
            }
        }
    }
    __syncthreads();

    // publish B: n = tanh(xn' + r*hn')
    if (w >= 10) {
#pragma unroll
        for (int j = 0; j < 3; ++j) {
            const int R = w * 48 + j * 16;
            if (R < 512) continue;
#pragma unroll
            for (int n = 0; n < 2; ++n) {
                const int col = n * 8 + cp2;
                if (col >= TG) continue;
                const float* cxp = &cx[(j * 2 + n) * 4];
                const float* chp = &ch[(j * 2 + n) * 4];
                const int q0 = R - 512 + r0, q1 = q0 + 8;
                float2 rv0 = __half22float2(*(const __half2*)&srz[q0 * TG + col]);
                float2 rv1 = __half22float2(*(const __half2*)&srz[q1 * TG + col]);
                *(__half2*)&sn[q0 * TG + col] =
                    __floats2half2_rn(tanhf_(cxp[0] + rv0.x * chp[0]),
                                      tanhf_(cxp[1] + rv0.y * chp[1]));
                *(__half2*)&sn[q1 * TG + col] =
                    __floats2half2_rn(tanhf_(cxp[2] + rv1.x * chp[2]),
                                      tanhf_(cxp[3] + rv1.y * chp[3]));
            }
        }
    }
    __syncthreads();
}

// ---------------- layer-1 pass: full 2-matrix GEMM (k16 chunks) + publish ----------------
__device__ __forceinline__ void gemm_pass1(
    const char* __restrict__ wsrc,      // blob-A layer1 + warp base
    const __half* __restrict__ opA,     // h0 (input) [16][OPW]
    const __half* __restrict__ opB,     // h1 (hidden) [16][OPW]
    __half* __restrict__ srz, __half* __restrict__ sn,
    const float* __restrict__ cbl, const float* __restrict__ hbl,
    u32 wstw, int w, int lane)
{
    float cx[24], ch[24];
#pragma unroll
    for (int i = 0; i < 24; ++i) { cx[i] = 0.f; ch[i] = 0.f; }

    const int loff = lane * 16;
    issue_chunk(wsrc, 0, wstw, 0, loff); CPA_COMMIT();
    issue_chunk(wsrc, 1, wstw, 1, loff); CPA_COMMIT();

    const int rowl = lane & 15;
    const u32 axor = (u32)((((lane >> 4) ^ ((rowl >> 2) & 1))) * 16);
    const int bof  = (lane >> 2) * OPW + (lane & 3) * 2;

#pragma unroll 1
    for (int i = 0; i < 16; ++i) {
        if (i + 2 < 16) issue_chunk(wsrc, i + 2, wstw, (i + 2) % 3, loff);
        CPA_COMMIT();
        CPA_WAIT2();
        const u32 sbase = wstw + (i % 3) * WCHUNK;
        const int kh = i * 16;
        const u32 bx0 = *(const u32*)(opA + bof + kh);
        const u32 bx1 = *(const u32*)(opA + bof + kh + 8);
        const u32 by0 = *(const u32*)(opA + bof + 8 * OPW + kh);
        const u32 by1 = *(const u32*)(opA + bof + 8 * OPW + kh + 8);
        const u32 hx0 = *(const u32*)(opB + bof + kh);
        const u32 hx1 = *(const u32*)(opB + bof + kh + 8);
        const u32 hy0 = *(const u32*)(opB + bof + 8 * OPW + kh);
        const u32 hy1 = *(const u32*)(opB + bof + 8 * OPW + kh + 8);
#pragma unroll
        for (int j = 0; j < 3; ++j) {
            const u32 ra = sbase + (u32)((j * 16 + rowl) * 32) + axor;
            u32 a0, a1, a2, a3;
            ldsm_x4(a0, a1, a2, a3, ra);
            mma16(&cx[(j * 2 + 0) * 4], a0, a1, a2, a3, bx0, bx1);
            mma16(&cx[(j * 2 + 1) * 4], a0, a1, a2, a3, by0, by1);
            ldsm_x4(a0, a1, a2, a3, ra + 1536);
            mma16(&ch[(j * 2 + 0) * 4], a0, a1, a2, a3, hx0, hx1);
            mma16(&ch[(j * 2 + 1) * 4], a0, a1, a2, a3, hy0, hy1);
        }
    }

    const int r0 = lane >> 2, cp2 = (lane & 3) * 2;
#pragma unroll
    for (int j = 0; j < 3; ++j) {
        const int R = w * 48 + j * 16;
#pragma unroll
        for (int n = 0; n < 2; ++n) {
            const int col = n * 8 + cp2;
            float* cxp = &cx[(j * 2 + n) * 4];
            float* chp = &ch[(j * 2 + n) * 4];
            if (R < 512) {
                if (col < TG) {
                    const int d0 = R + r0, d1 = d0 + 8;
                    *(__half2*)&srz[d0 * TG + col] =
                        __floats2half2_rn(sigmoidf_(cxp[0] + chp[0] + cbl[d0]),
                                          sigmoidf_(cxp[1] + chp[1] + cbl[d0]));
                    *(__half2*)&srz[d1 * TG + col] =
                        __floats2half2_rn(sigmoidf_(cxp[2] + chp[2] + cbl[d1]),
                                          sigmoidf_(cxp[3] + chp[3] + cbl[d1]));
                }
            } else {
                const int q0 = R - 512 + r0, q1 = q0 + 8;
                cxp[0] += cbl[512 + q0]; cxp[1] += cbl[512 + q0];
                cxp[2] += cbl[512 + q1]; cxp[3] += cbl[512 + q1];
                chp[0] += hbl[q0];       chp[1] += hbl[q0];
                chp[2] += hbl[q1];       chp[3] += hbl[q1];
            }
        }
    }
    __syncthreads();

    if (w >= 10) {
#pragma unroll
        for (int j = 0; j < 3; ++j) {
            const int R = w * 48 + j * 16;
            if (R < 512) continue;
#pragma unroll
            for (int n = 0; n < 2; ++n) {
                const int col = n * 8 + cp2;
                if (col >= TG) continue;
                const float* cxp = &cx[(j * 2 + n) * 4];
                const float* chp = &ch[(j * 2 + n) * 4];
                const int q0 = R - 512 + r0, q1 = q0 + 8;
                float2 rv0 = __half22float2(*(const __half2*)&srz[q0 * TG + col]);
                float2 rv1 = __half22float2(*(const __half2*)&srz[q1 * TG + col]);
                *(__half2*)&sn[q0 * TG + col] =
                    __floats2half2_rn(tanhf_(cxp[0] + rv0.x * chp[0]),
                                      tanhf_(cxp[1] + rv0.y * chp[1]));
                *(__half2*)&sn[q1 * TG + col] =
                    __floats2half2_rn(tanhf_(cxp[2] + rv1.x * chp[2]),
                                      tanhf_(cxp[3] + rv1.y * chp[3]));
            }
        }
    }
    __syncthreads();
}

// ---------------- main persistent kernel ----------------
__global__ __launch_bounds__(NT, 1) void gru_main(
    const float* __restrict__ bih0, const float* __restrict__ bhh0,
    const float* __restrict__ bih1, const float* __restrict__ bhh1,
    float* __restrict__ out, int B)
{
    extern __shared__ char sb[];
    __half* xps = (__half*)(sb + OFF_XPS);
    __half* h0h = (__half*)(sb + OFF_H0H);
    __half* h1h = (__half*)(sb + OFF_H1H);
    __half* srz = (__half*)(sb + OFF_SRZ);
    __half* sn  = (__half*)(sb + OFF_SN);
    float*  cb  = (float*)(sb + OFF_CB);
    float*  hb  = (float*)(sb + OFF_HB);

    const int tid  = threadIdx.x;
    const int w    = tid >> 5;
    const int lane = tid & 31;
    const int d    = tid & 255;
    const int gb   = tid >> 8;          // 0 or 1
    const int g0   = blockIdx.x * TG;

    const u32 wstw = (u32)__cvta_generic_to_shared(sb + OFF_W) + (u32)(w * WSTAGES);
    const char* whh0w = (const char*)g_whh0            + (size_t)w * 24576;
    const char* wb1w  = (const char*)(g_wblob + 393216) + (size_t)w * 49152;

    // biases -> smem
    for (int i = tid; i < GD; i += NT) {
        cb[i]      = (i < 512) ? bih0[i] + bhh0[i] : bih0[i];
        cb[GD + i] = (i < 512) ? bih1[i] + bhh1[i] : bih1[i];
    }
    for (int i = tid; i < DD; i += NT) {
        hb[i]      = bhh0[512 + i];
        hb[DD + i] = bhh1[512 + i];
    }
    // zero h operand halves (h0h+h1h contiguous: 2*8448 B = 4224 u32)
    for (int i = tid; i < 4224; i += NT) ((u32*)h0h)[i] = 0;
    __syncthreads();

    // gather xp(0)
    for (int q = tid; q < 1536; q += NT) {
        const int g = q / 96, off = q % 96;
        const int grp = g0 + g;
        const int e = (g < TG && grp < B) ? g_order[grp * LL] : -1;
        uint4 v = (e >= 0) ? *(const uint4*)(g_xp + (size_t)e * GD + off * 8)
                           : make_uint4(0, 0, 0, 0);
        *(uint4*)((char*)xps + g * (XPW * 2) + off * 16) = v;
    }

    float h0r[7], h1r[7], acc[7];
#pragma unroll
    for (int i = 0; i < 7; ++i) { h0r[i] = 0.f; h1r[i] = 0.f; acc[i] = 0.f; }
    __syncthreads();

#pragma unroll 1
    for (int t = 0; t < LL; ++t) {
        // ---- layer 0: hh GEMM + xp combine ----
        gemm_pass0(whh0w, h0h, xps, srz, sn, cb, hb, wstw, w, lane);
#pragma unroll
        for (int i = 0; i < 7; ++i) {
            const int g = gb + 2 * i;
            float z = __half2float(srz[(256 + d) * TG + g]);
            float n = __half2float(sn[d * TG + g]);
            float h = h0r[i];
            float hn2 = n + z * (h - n);
            h0r[i] = hn2;
            h0h[g * OPW + d] = __float2half_rn(hn2);
        }
        __syncthreads();    // h0h stable before layer-1 B loads

        // ---- layer 1 ----
        gemm_pass1(wb1w, h0h, h1h, srz, sn, cb + GD, hb + DD, wstw, w, lane);
#pragma unroll
        for (int i = 0; i < 7; ++i) {
            const int g = gb + 2 * i;
            float z = __half2float(srz[(256 + d) * TG + g]);
            float n = __half2float(sn[d * TG + g]);
            float h = h1r[i];
            float hn2 = n + z * (h - n);
            h1r[i] = hn2;
            acc[i] += hn2;
            h1h[g * OPW + d] = __float2half_rn(hn2);
        }
        if (t + 1 < LL) {
            for (int q = tid; q < 1536; q += NT) {
                const int g = q / 96, off = q % 96;
                const int grp = g0 + g;
                const int e = (g < TG && grp < B) ? g_order[grp * LL + t + 1] : -1;
                uint4 v = (e >= 0) ? *(const uint4*)(g_xp + (size_t)e * GD + off * 8)
                                   : make_uint4(0, 0, 0, 0);
                *(uint4*)((char*)xps + g * (XPW * 2) + off * 16) = v;
            }
        }
        __syncthreads();    // xps/h1h stable before next step
    }

#pragma unroll
    for (int i = 0; i < 7; ++i) {
        const int grp = g0 + gb + 2 * i;
        if (grp < B) out[(size_t)grp * DD + d] = acc[i] * (1.0f / LL);
    }
}

// ---------------- entry point ----------------
extern "C" void kernel_launch(void* const* d_in, const int* in_sizes, int n_in,
                              void* d_out, int out_size) {
    const float* x     = (const float*)d_in[0];
    const float* ts    = (const float*)d_in[1];
    const float* wih0  = (const float*)d_in[2];
    const float* whh0  = (const float*)d_in[3];
    const float* bih0  = (const float*)d_in[4];
    const float* bhh0  = (const float*)d_in[5];
    const float* wih1  = (const float*)d_in[6];
    const float* whh1  = (const float*)d_in[7];
    const float* bih1  = (const float*)d_in[8];
    const float* bhh1  = (const float*)d_in[9];
    const int*   index = (const int*)d_in[10];
    float* out = (float*)d_out;

    const int E = in_sizes[0] / DD;
    const int B = out_size / DD;

    cudaFuncSetAttribute(gru_main, cudaFuncAttributeMaxDynamicSharedMemorySize, SMEM_TOT);
    cudaFuncSetAttribute(xp_k, cudaFuncAttributeMaxDynamicSharedMemorySize, XP_SMEM);

    // setup: [0,B) group sorts, then both weight blobs (983040 elems / 256)
    setup_k<<<B + 3840, 256>>>(ts, index, E, B, wih0, whh0, wih1, whh1);

    // precompute xp = W_ih0 @ x
    xp_k<<<(E + 63) / 64, NT, XP_SMEM>>>(x, E);

    int nb = (B + TG - 1) / TG;
    if (nb < 148) nb = 148;
    gru_main<<<nb, NT, SMEM_TOT>>>(bih0, bhh0, bih1, bhh1, out, B);
}